// round 3
// baseline (speedup 1.0000x reference)
#include <cuda_runtime.h>
#include <math.h>

#define NT_   32768
#define B_    16
#define N_    2048
#define INCH_ 128
#define H_    4
#define C_    64
#define HC_   256
#define E_    524288
#define FC0_  1024
#define FC1_  512
#define OMIC_ 128
#define OUT_  2

// ---------------- scratch (static device globals; no runtime alloc) -------
__device__ __align__(16) float g_xw[NT_ * HC_];       // x @ W  (per layer)
__device__ __align__(16) float g_h [NT_ * HC_];       // elu(GAT1 out)
__device__ __align__(16) float g_asrc[NT_ * 4];
__device__ __align__(16) float g_adst[NT_ * 4];
__device__ int   g_deg[NT_];
__device__ int   g_cur[NT_];
__device__ int   g_row[NT_ + 1];
__device__ int   g_csr[E_];
__device__ __align__(16) float g_feat[B_ * 3 * N_];   // [B, 3N]
__device__ __align__(16) float g_e0[B_ * FC0_];
__device__ __align__(16) float g_e1[B_ * FC1_];
__device__ __align__(16) float g_e2[B_ * OMIC_];
__device__ int   g_i64;                                // edge_index dtype flag

__device__ __forceinline__ float elu1(float x)  { return x > 0.f ? x : (expf(x) - 1.f); }
__device__ __forceinline__ float lrelu(float x) { return x > 0.f ? x : 0.2f * x; }

// robust index load: works for int32 or int64 edge_index
__device__ __forceinline__ int ld_idx(const void* ei, int i) {
    if (g_i64) return (int)((const long long*)ei)[i];
    return ((const int*)ei)[i];
}

// ---------------- dtype detection -----------------------------------------
__global__ void k_detect(const void* ei) {
    if (threadIdx.x == 0) {
        const long long* p64 = (const long long*)ei;
        int ok64 = 1;
        for (int i = 0; i < 32; i++) {
            long long v = p64[i];
            if (v < 0 || v >= NT_) { ok64 = 0; break; }
        }
        g_i64 = ok64;
    }
}

// ---------------- zero scratch that accumulates ---------------------------
__global__ void k_zero() {
    int i = blockIdx.x * blockDim.x + threadIdx.x;   // 32768 threads
    if (i < NT_)        { g_deg[i] = 0; g_cur[i] = 0; }
    if (i < B_ * FC0_)  g_e0[i] = 0.f;
    if (i < B_ * FC1_)  g_e1[i] = 0.f;
    if (i < B_ * OMIC_) g_e2[i] = 0.f;
}

// ---------------- CSR build (by dst) --------------------------------------
__global__ void k_deg(const void* __restrict__ ei) {
    int e = blockIdx.x * blockDim.x + threadIdx.x;
    if (e < E_) {
        int d = ld_idx(ei, E_ + e) & (NT_ - 1);
        atomicAdd(&g_deg[d], 1);
    }
}

__global__ void k_scan() {   // 1 block, 1024 threads, 32 elems each
    __shared__ int part[1024];
    int t = threadIdx.x;
    int base = t * 32;
    int loc[32];
    int s = 0;
#pragma unroll
    for (int i = 0; i < 32; i++) { loc[i] = g_deg[base + i]; s += loc[i]; }
    part[t] = s;
    __syncthreads();
    for (int off = 1; off < 1024; off <<= 1) {
        int v = (t >= off) ? part[t - off] : 0;
        __syncthreads();
        part[t] += v;
        __syncthreads();
    }
    int run = (t == 0) ? 0 : part[t - 1];
#pragma unroll
    for (int i = 0; i < 32; i++) { g_row[base + i] = run; run += loc[i]; }
    if (t == 1023) g_row[NT_] = run;   // == E_
}

__global__ void k_scatter(const void* __restrict__ ei) {
    int e = blockIdx.x * blockDim.x + threadIdx.x;
    if (e < E_) {
        int d = ld_idx(ei, E_ + e) & (NT_ - 1);
        int s = ld_idx(ei, e) & (NT_ - 1);
        int pos = g_row[d] + atomicAdd(&g_cur[d], 1);
        g_csr[pos] = s;
    }
}

// canonical (deterministic) order within each dst segment: sort by src id
__global__ void k_sortseg() {
    int n = blockIdx.x * blockDim.x + threadIdx.x;
    if (n >= NT_) return;
    int r0 = g_row[n], r1 = g_row[n + 1];
    for (int i = r0 + 1; i < r1; i++) {
        int v = g_csr[i];
        int j = i - 1;
        while (j >= r0 && g_csr[j] > v) { g_csr[j + 1] = g_csr[j]; j--; }
        g_csr[j + 1] = v;
    }
}

// ---------------- SGEMM: [NT,K] @ [K,256] -> g_xw -------------------------
// BM=128, BN=128, BK=16, 256 threads, 8x8 per thread
__global__ __launch_bounds__(256, 2)
void k_gemm(const float* __restrict__ Aext, int useH,
            const float* __restrict__ W, int K) {
    const float* A = useH ? (const float*)g_h : Aext;
    __shared__ float As[16][128];
    __shared__ float Bs[16][128];
    int tid = threadIdx.x;
    int tx = tid & 15, ty = tid >> 4;
    int aRow = tid >> 2, aCol = (tid & 3) << 2;
    int bRow = tid >> 5, bCol = (tid & 31) << 2;
    const float* Ab = A + (size_t)blockIdx.x * 128 * K;
    const float* Wb = W + blockIdx.y * 128;
    float acc[8][8];
#pragma unroll
    for (int i = 0; i < 8; i++)
#pragma unroll
        for (int j = 0; j < 8; j++) acc[i][j] = 0.f;

    for (int k0 = 0; k0 < K; k0 += 16) {
        float4 a0 = *(const float4*)(Ab + (size_t)aRow        * K + k0 + aCol);
        float4 a1 = *(const float4*)(Ab + (size_t)(aRow + 64) * K + k0 + aCol);
        float4 b0 = *(const float4*)(Wb + (size_t)(k0 + bRow)     * HC_ + bCol);
        float4 b1 = *(const float4*)(Wb + (size_t)(k0 + bRow + 8) * HC_ + bCol);
        As[aCol + 0][aRow] = a0.x; As[aCol + 1][aRow] = a0.y;
        As[aCol + 2][aRow] = a0.z; As[aCol + 3][aRow] = a0.w;
        As[aCol + 0][aRow + 64] = a1.x; As[aCol + 1][aRow + 64] = a1.y;
        As[aCol + 2][aRow + 64] = a1.z; As[aCol + 3][aRow + 64] = a1.w;
        *(float4*)&Bs[bRow][bCol]     = b0;
        *(float4*)&Bs[bRow + 8][bCol] = b1;
        __syncthreads();
#pragma unroll
        for (int kk = 0; kk < 16; kk++) {
            float4 ra0 = *(const float4*)&As[kk][ty * 8];
            float4 ra1 = *(const float4*)&As[kk][ty * 8 + 4];
            float4 rb0 = *(const float4*)&Bs[kk][tx * 8];
            float4 rb1 = *(const float4*)&Bs[kk][tx * 8 + 4];
            float ra[8] = {ra0.x, ra0.y, ra0.z, ra0.w, ra1.x, ra1.y, ra1.z, ra1.w};
            float rb[8] = {rb0.x, rb0.y, rb0.z, rb0.w, rb1.x, rb1.y, rb1.z, rb1.w};
#pragma unroll
            for (int i = 0; i < 8; i++)
#pragma unroll
                for (int j = 0; j < 8; j++) acc[i][j] += ra[i] * rb[j];
        }
        __syncthreads();
    }
    int rowC = blockIdx.x * 128 + ty * 8;
    int colC = blockIdx.y * 128 + tx * 8;
#pragma unroll
    for (int i = 0; i < 8; i++) {
        float4 o0 = {acc[i][0], acc[i][1], acc[i][2], acc[i][3]};
        float4 o1 = {acc[i][4], acc[i][5], acc[i][6], acc[i][7]};
        *(float4*)(g_xw + (size_t)(rowC + i) * HC_ + colC)     = o0;
        *(float4*)(g_xw + (size_t)(rowC + i) * HC_ + colC + 4) = o1;
    }
}

// ---------------- attention dots: a_src/a_dst per (node, head) ------------
__global__ void k_attn(const float* __restrict__ att_s,
                       const float* __restrict__ att_d) {
    int gw = (blockIdx.x * blockDim.x + threadIdx.x) >> 5;
    int lane = threadIdx.x & 31;
    if (gw >= NT_) return;
    const float4* xp = (const float4*)(g_xw + (size_t)gw * HC_ + lane * 8);
    const float4* sp = (const float4*)(att_s + lane * 8);
    const float4* dp = (const float4*)(att_d + lane * 8);
    float4 x0 = xp[0], x1 = xp[1];
    float4 s0 = sp[0], s1 = sp[1];
    float4 d0 = dp[0], d1 = dp[1];
    float ps = x0.x*s0.x + x0.y*s0.y + x0.z*s0.z + x0.w*s0.w
             + x1.x*s1.x + x1.y*s1.y + x1.z*s1.z + x1.w*s1.w;
    float pd = x0.x*d0.x + x0.y*d0.y + x0.z*d0.z + x0.w*d0.w
             + x1.x*d1.x + x1.y*d1.y + x1.z*d1.z + x1.w*d1.w;
#pragma unroll
    for (int off = 4; off >= 1; off >>= 1) {
        ps += __shfl_down_sync(0xffffffffu, ps, off);
        pd += __shfl_down_sync(0xffffffffu, pd, off);
    }
    if ((lane & 7) == 0) {
        int h = lane >> 3;
        g_asrc[gw * 4 + h] = ps;
        g_adst[gw * 4 + h] = pd;
    }
}

// ---------------- GAT aggregation (warp per node, CSR) --------------------
__global__ void k_agg(const float* __restrict__ bias,
                      const float* __restrict__ poolw,
                      const float* __restrict__ poolb,
                      int writeH, int seg) {
    int n = (blockIdx.x * blockDim.x + threadIdx.x) >> 5;
    int lane = threadIdx.x & 31;
    if (n >= NT_) return;
    int h = lane >> 3;

    float4 d4 = *(const float4*)(g_adst + n * 4);
    float4 s4 = *(const float4*)(g_asrc + n * 4);
    float adh = (h == 0) ? d4.x : (h == 1) ? d4.y : (h == 2) ? d4.z : d4.w;

    int r0 = g_row[n], r1 = g_row[n + 1];

    float4 eself;
    eself.x = __expf(lrelu(s4.x + d4.x));
    eself.y = __expf(lrelu(s4.y + d4.y));
    eself.z = __expf(lrelu(s4.z + d4.z));
    eself.w = __expf(lrelu(s4.w + d4.w));

    // pass 1: denominator
    float4 den = {0.f, 0.f, 0.f, 0.f};
    for (int idx = r0 + lane; idx < r1; idx += 32) {
        int s = g_csr[idx];
        float4 a = *(const float4*)(g_asrc + s * 4);
        den.x += __expf(lrelu(a.x + d4.x));
        den.y += __expf(lrelu(a.y + d4.y));
        den.z += __expf(lrelu(a.z + d4.z));
        den.w += __expf(lrelu(a.w + d4.w));
    }
#pragma unroll
    for (int off = 16; off >= 1; off >>= 1) {
        den.x += __shfl_xor_sync(0xffffffffu, den.x, off);
        den.y += __shfl_xor_sync(0xffffffffu, den.y, off);
        den.z += __shfl_xor_sync(0xffffffffu, den.z, off);
        den.w += __shfl_xor_sync(0xffffffffu, den.w, off);
    }
    den.x += eself.x; den.y += eself.y; den.z += eself.z; den.w += eself.w;

    float denh = (h == 0) ? den.x : (h == 1) ? den.y : (h == 2) ? den.z : den.w;
    float rden = 1.f / (denh + 1e-16f);
    float esh  = (h == 0) ? eself.x : (h == 1) ? eself.y : (h == 2) ? eself.z : eself.w;

    // pass 2: weighted accumulate (8 channels per lane)
    float wself = esh * rden;
    const float4* xp = (const float4*)(g_xw + (size_t)n * HC_ + lane * 8);
    float4 q0 = xp[0], q1 = xp[1];
    float4 acc0 = {wself*q0.x, wself*q0.y, wself*q0.z, wself*q0.w};
    float4 acc1 = {wself*q1.x, wself*q1.y, wself*q1.z, wself*q1.w};

    for (int e = r0; e < r1; e++) {
        int s = g_csr[e];
        float as = g_asrc[s * 4 + h];
        float wgt = __expf(lrelu(as + adh)) * rden;
        const float4* q = (const float4*)(g_xw + (size_t)s * HC_ + lane * 8);
        float4 a = q[0], b = q[1];
        acc0.x += wgt * a.x; acc0.y += wgt * a.y;
        acc0.z += wgt * a.z; acc0.w += wgt * a.w;
        acc1.x += wgt * b.x; acc1.y += wgt * b.y;
        acc1.z += wgt * b.z; acc1.w += wgt * b.w;
    }

    const float* bp = bias + lane * 8;
    float v[8];
    v[0] = elu1(acc0.x + bp[0]); v[1] = elu1(acc0.y + bp[1]);
    v[2] = elu1(acc0.z + bp[2]); v[3] = elu1(acc0.w + bp[3]);
    v[4] = elu1(acc1.x + bp[4]); v[5] = elu1(acc1.y + bp[5]);
    v[6] = elu1(acc1.z + bp[6]); v[7] = elu1(acc1.w + bp[7]);

    if (writeH) {
        float4 o0 = {v[0], v[1], v[2], v[3]};
        float4 o1 = {v[4], v[5], v[6], v[7]};
        *(float4*)(g_h + (size_t)n * HC_ + lane * 8)     = o0;
        *(float4*)(g_h + (size_t)n * HC_ + lane * 8 + 4) = o1;
    }

    const float* pw = poolw + lane * 8;
    float p = v[0]*pw[0] + v[1]*pw[1] + v[2]*pw[2] + v[3]*pw[3]
            + v[4]*pw[4] + v[5]*pw[5] + v[6]*pw[6] + v[7]*pw[7];
#pragma unroll
    for (int off = 16; off >= 1; off >>= 1)
        p += __shfl_xor_sync(0xffffffffu, p, off);
    if (lane == 0)
        g_feat[(n >> 11) * (3 * N_) + seg * N_ + (n & 2047)] = p + poolb[0];
}

// ---------------- x0: per-node mean of input features ---------------------
__global__ void k_x0(const float* __restrict__ x) {
    int n = (blockIdx.x * blockDim.x + threadIdx.x) >> 5;
    int lane = threadIdx.x & 31;
    if (n >= NT_) return;
    float4 v = *(const float4*)(x + (size_t)n * INCH_ + lane * 4);
    float s = v.x + v.y + v.z + v.w;
#pragma unroll
    for (int off = 16; off >= 1; off >>= 1)
        s += __shfl_xor_sync(0xffffffffu, s, off);
    if (lane == 0)
        g_feat[(n >> 11) * (3 * N_) + (n & 2047)] = s * (1.f / 128.f);
}

// ---------------- LayerNorm over each 2048-row of g_feat (in place) -------
__global__ void k_ln(const float* __restrict__ w, const float* __restrict__ b) {
    __shared__ float red[8];
    __shared__ float tot;
    int row = blockIdx.x;                          // 0..47
    float* p = g_feat + (row / 3) * (3 * N_) + (row % 3) * N_;
    int t = threadIdx.x;                           // 256
    float v[8];
    float s = 0.f;
#pragma unroll
    for (int i = 0; i < 8; i++) { v[i] = p[t + 256 * i]; s += v[i]; }
#pragma unroll
    for (int off = 16; off >= 1; off >>= 1) s += __shfl_xor_sync(0xffffffffu, s, off);
    if ((t & 31) == 0) red[t >> 5] = s;
    __syncthreads();
    if (t == 0) { float z = 0.f; for (int i = 0; i < 8; i++) z += red[i]; tot = z; }
    __syncthreads();
    float mu = tot * (1.f / 2048.f);
    float q = 0.f;
#pragma unroll
    for (int i = 0; i < 8; i++) { float d = v[i] - mu; q += d * d; }
#pragma unroll
    for (int off = 16; off >= 1; off >>= 1) q += __shfl_xor_sync(0xffffffffu, q, off);
    __syncthreads();
    if ((t & 31) == 0) red[t >> 5] = q;
    __syncthreads();
    if (t == 0) { float z = 0.f; for (int i = 0; i < 8; i++) z += red[i]; tot = z; }
    __syncthreads();
    float r = rsqrtf(tot * (1.f / 2048.f) + 1e-5f);
#pragma unroll
    for (int i = 0; i < 8; i++) {
        int idx = t + 256 * i;
        p[idx] = (v[i] - mu) * r * w[idx] + b[idx];
    }
}

// ---------------- FC partial GEMM: [16,K] @ [K,Ncol] accumulated ----------
__global__ void k_fc(int which, const float* __restrict__ W, int K, int Ncol) {
    const float* A = (which == 0) ? (const float*)g_feat
                   : (which == 1) ? (const float*)g_e0 : (const float*)g_e1;
    float* Cr      = (which == 0) ? g_e0 : (which == 1) ? g_e1 : g_e2;
    __shared__ float sa[16][128];
    int tid = threadIdx.x;                 // 128
    int j = blockIdx.x * 128 + tid;
    int kslab = K / gridDim.y;
    int k0 = blockIdx.y * kslab;
    float acc[16];
#pragma unroll
    for (int bi = 0; bi < 16; bi++) acc[bi] = 0.f;
    for (int kt = k0; kt < k0 + kslab; kt += 128) {
#pragma unroll
        for (int i = 0; i < 16; i++) sa[i][tid] = A[i * K + kt + tid];
        __syncthreads();
#pragma unroll 4
        for (int kk = 0; kk < 128; kk++) {
            float wv = W[(size_t)(kt + kk) * Ncol + j];
#pragma unroll
            for (int bi = 0; bi < 16; bi++) acc[bi] += sa[bi][kk] * wv;
        }
        __syncthreads();
    }
#pragma unroll
    for (int bi = 0; bi < 16; bi++) atomicAdd(&Cr[bi * Ncol + j], acc[bi]);
}

__global__ void k_bias_elu(int which, const float* __restrict__ bias, int Ncol) {
    float* C = (which == 0) ? g_e0 : (which == 1) ? g_e1 : g_e2;
    int i = blockIdx.x * blockDim.x + threadIdx.x;
    if (i < 16 * Ncol) C[i] = elu1(C[i] + bias[i % Ncol]);
}

__global__ void k_last(const float* __restrict__ lw, const float* __restrict__ lb,
                       float* __restrict__ out, int out_n) {
    int t = threadIdx.x;
    if (t < 32 && t < out_n) {
        int bi = t >> 1, o = t & 1;
        float a = 0.f;
        for (int k = 0; k < OMIC_; k++) a += g_e2[bi * OMIC_ + k] * lw[k * 2 + o];
        out[t] = a + lb[o];
    }
}

// ---------------- driver ---------------------------------------------------
extern "C" void kernel_launch(void* const* d_in, const int* in_sizes, int n_in,
                              void* d_out, int out_size) {
    const float* x   = (const float*)d_in[0];
    const void*  ei  = d_in[1];
    const float* w1  = (const float*)d_in[2];
    const float* as1 = (const float*)d_in[3];
    const float* ad1 = (const float*)d_in[4];
    const float* b1  = (const float*)d_in[5];
    const float* p1w = (const float*)d_in[6];
    const float* p1b = (const float*)d_in[7];
    const float* w2  = (const float*)d_in[8];
    const float* as2 = (const float*)d_in[9];
    const float* ad2 = (const float*)d_in[10];
    const float* b2  = (const float*)d_in[11];
    const float* p2w = (const float*)d_in[12];
    const float* p2b = (const float*)d_in[13];
    const float* lnw = (const float*)d_in[14];
    const float* lnb = (const float*)d_in[15];
    const float* e0w = (const float*)d_in[16];
    const float* e0b = (const float*)d_in[17];
    const float* e1w = (const float*)d_in[18];
    const float* e1b = (const float*)d_in[19];
    const float* e2w = (const float*)d_in[20];
    const float* e2b = (const float*)d_in[21];
    const float* lw  = (const float*)d_in[22];
    const float* lb  = (const float*)d_in[23];
    float* out = (float*)d_out;

    k_detect<<<1, 32>>>(ei);
    k_zero<<<128, 256>>>();
    k_deg<<<E_ / 256, 256>>>(ei);
    k_scan<<<1, 1024>>>();
    k_scatter<<<E_ / 256, 256>>>(ei);
    k_sortseg<<<NT_ / 256, 256>>>();

    // ---- GAT layer 1
    k_gemm<<<dim3(NT_ / 128, 2), 256>>>(x, 0, w1, INCH_);
    k_attn<<<NT_ / 8, 256>>>(as1, ad1);
    k_agg<<<NT_ / 8, 256>>>(b1, p1w, p1b, /*writeH=*/1, /*seg=*/1);

    // ---- GAT layer 2
    k_gemm<<<dim3(NT_ / 128, 2), 256>>>(nullptr, 1, w2, HC_);
    k_attn<<<NT_ / 8, 256>>>(as2, ad2);
    k_agg<<<NT_ / 8, 256>>>(b2, p2w, p2b, /*writeH=*/0, /*seg=*/2);

    // ---- x0 + LayerNorm
    k_x0<<<NT_ / 8, 256>>>(x);
    k_ln<<<48, 256>>>(lnw, lnb);

    // ---- FC encoder
    k_fc<<<dim3(FC0_ / 128, 6), 128>>>(0, e0w, 3 * N_, FC0_);
    k_bias_elu<<<(16 * FC0_ + 255) / 256, 256>>>(0, e0b, FC0_);
    k_fc<<<dim3(FC1_ / 128, 2), 128>>>(1, e1w, FC0_, FC1_);
    k_bias_elu<<<(16 * FC1_ + 255) / 256, 256>>>(1, e1b, FC1_);
    k_fc<<<dim3(OMIC_ / 128, 4), 128>>>(2, e2w, FC1_, OMIC_);
    k_bias_elu<<<(16 * OMIC_ + 255) / 256, 256>>>(2, e2b, OMIC_);
    k_last<<<1, 32>>>(lw, lb, out, out_size);
}

// round 4
// speedup vs baseline: 1.1140x; 1.1140x over previous
#include <cuda_runtime.h>
#include <math.h>

#define NT_   32768
#define B_    16
#define N_    2048
#define INCH_ 128
#define H_    4
#define C_    64
#define HC_   256
#define E_    524288
#define FC0_  1024
#define FC1_  512
#define OMIC_ 128
#define OUT_  2

// ---------------- scratch (static device globals) --------------------------
__device__ __align__(16) float g_xw[NT_ * HC_];
__device__ __align__(16) float g_h [NT_ * HC_];
__device__ __align__(16) float g_asrc[NT_ * 4];
__device__ __align__(16) float g_adst[NT_ * 4];
__device__ int   g_deg[NT_];
__device__ int   g_cur[NT_];
__device__ int   g_row[NT_ + 1];
__device__ int   g_blk[128];
__device__ int   g_blk2[128];
__device__ int   g_csr[E_];
__device__ __align__(16) float g_feat[B_ * 3 * N_];
__device__ __align__(16) float g_part[6 * B_ * FC0_];   // FC k-split partials
__device__ __align__(16) float g_e0[B_ * FC0_];
__device__ __align__(16) float g_e1[B_ * FC1_];
__device__ __align__(16) float g_e2[B_ * OMIC_];
__device__ int   g_i64;

__device__ __forceinline__ float elu1(float x)  { return x > 0.f ? x : (expf(x) - 1.f); }
__device__ __forceinline__ float lrelu(float x) { return x > 0.f ? x : 0.2f * x; }

__device__ __forceinline__ int ld_idx(const void* ei, int i) {
    if (g_i64) return (int)((const long long*)ei)[i];
    return ((const int*)ei)[i];
}

// ---------------- dtype detection ------------------------------------------
__global__ void k_detect(const void* ei) {
    if (threadIdx.x == 0) {
        const long long* p64 = (const long long*)ei;
        int ok64 = 1;
        for (int i = 0; i < 32; i++) {
            long long v = p64[i];
            if (v < 0 || v >= NT_) { ok64 = 0; break; }
        }
        g_i64 = ok64;
    }
}

__global__ void k_zero() {
    int i = blockIdx.x * blockDim.x + threadIdx.x;
    if (i < NT_) { g_deg[i] = 0; g_cur[i] = 0; }
}

// ---------------- CSR build (by dst) ---------------------------------------
__global__ void k_deg(const void* __restrict__ ei) {
    int e = blockIdx.x * blockDim.x + threadIdx.x;
    if (e < E_) atomicAdd(&g_deg[ld_idx(ei, E_ + e) & (NT_ - 1)], 1);
}

// hierarchical exclusive scan of g_deg -> g_row
__global__ void k_scan1() {            // 128 blocks x 256
    __shared__ int wt[8];
    int t = threadIdx.x;
    int i = blockIdx.x * 256 + t;
    int v = g_deg[i];
    int lane = t & 31, w = t >> 5;
    int inc = v;
#pragma unroll
    for (int off = 1; off < 32; off <<= 1) {
        int u = __shfl_up_sync(0xffffffffu, inc, off);
        if (lane >= off) inc += u;
    }
    if (lane == 31) wt[w] = inc;
    __syncthreads();
    if (t == 0) {
        int run = 0;
#pragma unroll
        for (int k = 0; k < 8; k++) { int x = wt[k]; wt[k] = run; run += x; }
        g_blk[blockIdx.x] = run;
    }
    __syncthreads();
    g_row[i] = inc - v + wt[w];
}

__global__ void k_scan2() {            // 1 block x 128
    __shared__ int wt[4];
    int t = threadIdx.x;
    int v = g_blk[t];
    int lane = t & 31, w = t >> 5;
    int inc = v;
#pragma unroll
    for (int off = 1; off < 32; off <<= 1) {
        int u = __shfl_up_sync(0xffffffffu, inc, off);
        if (lane >= off) inc += u;
    }
    if (lane == 31) wt[w] = inc;
    __syncthreads();
    if (t == 0) {
        int run = 0;
#pragma unroll
        for (int k = 0; k < 4; k++) { int x = wt[k]; wt[k] = run; run += x; }
        g_row[NT_] = run;              // == E_
    }
    __syncthreads();
    g_blk2[t] = inc - v + wt[w];
}

__global__ void k_scan3() {            // 128 blocks x 256
    int i = blockIdx.x * 256 + threadIdx.x;
    g_row[i] += g_blk2[blockIdx.x];
}

__global__ void k_scatter(const void* __restrict__ ei) {
    int e = blockIdx.x * blockDim.x + threadIdx.x;
    if (e < E_) {
        int d = ld_idx(ei, E_ + e) & (NT_ - 1);
        int s = ld_idx(ei, e) & (NT_ - 1);
        int pos = g_row[d] + atomicAdd(&g_cur[d], 1);
        g_csr[pos] = s;
    }
}

// deterministic order within segment: sort by src id (L1-local buffer)
__global__ void k_sortseg() {
    int n = blockIdx.x * blockDim.x + threadIdx.x;
    if (n >= NT_) return;
    int r0 = g_row[n], r1 = g_row[n + 1];
    int len = r1 - r0;
    if (len <= 1) return;
    if (len <= 96) {
        int buf[96];
        for (int i = 0; i < len; i++) buf[i] = g_csr[r0 + i];
        for (int i = 1; i < len; i++) {
            int v = buf[i]; int j = i - 1;
            while (j >= 0 && buf[j] > v) { buf[j + 1] = buf[j]; j--; }
            buf[j + 1] = v;
        }
        for (int i = 0; i < len; i++) g_csr[r0 + i] = buf[i];
    } else {
        for (int i = r0 + 1; i < r1; i++) {
            int v = g_csr[i]; int j = i - 1;
            while (j >= r0 && g_csr[j] > v) { g_csr[j + 1] = g_csr[j]; j--; }
            g_csr[j + 1] = v;
        }
    }
}

// ---------------- 3xTF32 tensor-core GEMM: [NT,K]@[K,256] -> g_xw ----------
// block 128x128, 256 threads (8 warps as 4x2), warp tile 32x64, K chunk 32
__device__ __forceinline__ void split_tf32(float x, unsigned& hi, unsigned& lo) {
    unsigned h;
    asm("cvt.rna.tf32.f32 %0, %1;" : "=r"(h) : "f"(x));
    float l = x - __uint_as_float(h);
    unsigned lu;
    asm("cvt.rna.tf32.f32 %0, %1;" : "=r"(lu) : "f"(l));
    hi = h; lo = lu;
}

__device__ __forceinline__ void mma8(float* c, unsigned a0, unsigned a1,
                                     unsigned a2, unsigned a3,
                                     unsigned b0, unsigned b1) {
    asm volatile(
        "mma.sync.aligned.m16n8k8.row.col.f32.tf32.tf32.f32 "
        "{%0,%1,%2,%3},{%4,%5,%6,%7},{%8,%9},{%0,%1,%2,%3};"
        : "+f"(c[0]), "+f"(c[1]), "+f"(c[2]), "+f"(c[3])
        : "r"(a0), "r"(a1), "r"(a2), "r"(a3), "r"(b0), "r"(b1));
}

__global__ __launch_bounds__(256, 2)
void k_gemm_tc(const float* __restrict__ Aext, int useH,
               const float* __restrict__ W, int K) {
    const float* A = useH ? (const float*)g_h : Aext;
    __shared__ float As[128][40];   // [m][k]  (pad 40: 16B-aligned rows)
    __shared__ float Bs[32][136];   // [k][n]
    int tid = threadIdx.x;
    int lid = tid & 31, wid = tid >> 5;
    int wr = wid >> 1, wc = wid & 1;          // 4x2 warps
    int g4 = lid >> 2, t4 = lid & 3;          // groupID / threadID-in-group

    const float* Ab = A + (size_t)blockIdx.x * 128 * K;
    const float* Wb = W + blockIdx.y * 128;

    float c[2][8][4];
#pragma unroll
    for (int mt = 0; mt < 2; mt++)
#pragma unroll
        for (int nt = 0; nt < 8; nt++)
#pragma unroll
            for (int q = 0; q < 4; q++) c[mt][nt][q] = 0.f;

    for (int k0 = 0; k0 < K; k0 += 32) {
        // load A tile 128x32
#pragma unroll
        for (int i = 0; i < 4; i++) {
            int id = tid + 256 * i;            // 0..1023
            int row = id >> 3, kq = id & 7;
            float4 v = *(const float4*)(Ab + (size_t)row * K + k0 + kq * 4);
            *(float4*)&As[row][kq * 4] = v;
        }
        // load B tile 32x128
#pragma unroll
        for (int i = 0; i < 4; i++) {
            int id = tid + 256 * i;
            int kr = id >> 5, cq = id & 31;
            float4 v = *(const float4*)(Wb + (size_t)(k0 + kr) * HC_ + cq * 4);
            *(float4*)&Bs[kr][cq * 4] = v;
        }
        __syncthreads();

#pragma unroll
        for (int ks = 0; ks < 4; ks++) {
            int kc = ks * 8 + t4;
            unsigned ah[2][4], al[2][4];
#pragma unroll
            for (int mt = 0; mt < 2; mt++) {
                int m = wr * 32 + mt * 16 + g4;
                split_tf32(As[m][kc],         ah[mt][0], al[mt][0]);
                split_tf32(As[m + 8][kc],     ah[mt][1], al[mt][1]);
                split_tf32(As[m][kc + 4],     ah[mt][2], al[mt][2]);
                split_tf32(As[m + 8][kc + 4], ah[mt][3], al[mt][3]);
            }
#pragma unroll
            for (int nt = 0; nt < 8; nt++) {
                int n = wc * 64 + nt * 8 + g4;
                unsigned bh0, bl0, bh1, bl1;
                split_tf32(Bs[ks * 8 + t4][n],     bh0, bl0);
                split_tf32(Bs[ks * 8 + t4 + 4][n], bh1, bl1);
#pragma unroll
                for (int mt = 0; mt < 2; mt++) {
                    mma8(c[mt][nt], ah[mt][0], ah[mt][1], ah[mt][2], ah[mt][3], bh0, bh1);
                    mma8(c[mt][nt], ah[mt][0], ah[mt][1], ah[mt][2], ah[mt][3], bl0, bl1);
                    mma8(c[mt][nt], al[mt][0], al[mt][1], al[mt][2], al[mt][3], bh0, bh1);
                }
            }
        }
        __syncthreads();
    }

    // epilogue
#pragma unroll
    for (int mt = 0; mt < 2; mt++) {
#pragma unroll
        for (int nt = 0; nt < 8; nt++) {
            int row = blockIdx.x * 128 + wr * 32 + mt * 16 + g4;
            int col = blockIdx.y * 128 + wc * 64 + nt * 8 + 2 * t4;
            float2 v0 = {c[mt][nt][0], c[mt][nt][1]};
            float2 v1 = {c[mt][nt][2], c[mt][nt][3]};
            *(float2*)(g_xw + (size_t)row * HC_ + col)       = v0;
            *(float2*)(g_xw + (size_t)(row + 8) * HC_ + col) = v1;
        }
    }
}

// ---------------- attention dots -------------------------------------------
__global__ void k_attn(const float* __restrict__ att_s,
                       const float* __restrict__ att_d) {
    int gw = (blockIdx.x * blockDim.x + threadIdx.x) >> 5;
    int lane = threadIdx.x & 31;
    if (gw >= NT_) return;
    const float4* xp = (const float4*)(g_xw + (size_t)gw * HC_ + lane * 8);
    const float4* sp = (const float4*)(att_s + lane * 8);
    const float4* dp = (const float4*)(att_d + lane * 8);
    float4 x0 = xp[0], x1 = xp[1];
    float4 s0 = sp[0], s1 = sp[1];
    float4 d0 = dp[0], d1 = dp[1];
    float ps = x0.x*s0.x + x0.y*s0.y + x0.z*s0.z + x0.w*s0.w
             + x1.x*s1.x + x1.y*s1.y + x1.z*s1.z + x1.w*s1.w;
    float pd = x0.x*d0.x + x0.y*d0.y + x0.z*d0.z + x0.w*d0.w
             + x1.x*d1.x + x1.y*d1.y + x1.z*d1.z + x1.w*d1.w;
#pragma unroll
    for (int off = 4; off >= 1; off >>= 1) {
        ps += __shfl_down_sync(0xffffffffu, ps, off);
        pd += __shfl_down_sync(0xffffffffu, pd, off);
    }
    if ((lane & 7) == 0) {
        int h = lane >> 3;
        g_asrc[gw * 4 + h] = ps;
        g_adst[gw * 4 + h] = pd;
    }
}

// ---------------- GAT aggregation: SINGLE pass (normalize at end) ----------
__global__ void k_agg(const float* __restrict__ bias,
                      const float* __restrict__ poolw,
                      const float* __restrict__ poolb,
                      int writeH, int seg) {
    int n = (blockIdx.x * blockDim.x + threadIdx.x) >> 5;
    int lane = threadIdx.x & 31;
    if (n >= NT_) return;
    int h = lane >> 3;

    float4 d4 = *(const float4*)(g_adst + n * 4);
    float4 s4 = *(const float4*)(g_asrc + n * 4);
    float adh = (h == 0) ? d4.x : (h == 1) ? d4.y : (h == 2) ? d4.z : d4.w;
    float ash = (h == 0) ? s4.x : (h == 1) ? s4.y : (h == 2) ? s4.z : s4.w;

    int r0 = g_row[n], r1 = g_row[n + 1];

    // self-loop
    float wself = __expf(lrelu(ash + adh));
    float den = wself;
    const float4* xp = (const float4*)(g_xw + (size_t)n * HC_ + lane * 8);
    float4 q0 = xp[0], q1 = xp[1];
    float4 acc0 = {wself*q0.x, wself*q0.y, wself*q0.z, wself*q0.w};
    float4 acc1 = {wself*q1.x, wself*q1.y, wself*q1.z, wself*q1.w};

    for (int e = r0; e < r1; e++) {
        int s = g_csr[e];
        float as = g_asrc[s * 4 + h];
        float wgt = __expf(lrelu(as + adh));
        den += wgt;
        const float4* q = (const float4*)(g_xw + (size_t)s * HC_ + lane * 8);
        float4 a = q[0], b = q[1];
        acc0.x += wgt * a.x; acc0.y += wgt * a.y;
        acc0.z += wgt * a.z; acc0.w += wgt * a.w;
        acc1.x += wgt * b.x; acc1.y += wgt * b.y;
        acc1.z += wgt * b.z; acc1.w += wgt * b.w;
    }
    float rden = 1.f / (den + 1e-16f);
    acc0.x *= rden; acc0.y *= rden; acc0.z *= rden; acc0.w *= rden;
    acc1.x *= rden; acc1.y *= rden; acc1.z *= rden; acc1.w *= rden;

    const float* bp = bias + lane * 8;
    float v[8];
    v[0] = elu1(acc0.x + bp[0]); v[1] = elu1(acc0.y + bp[1]);
    v[2] = elu1(acc0.z + bp[2]); v[3] = elu1(acc0.w + bp[3]);
    v[4] = elu1(acc1.x + bp[4]); v[5] = elu1(acc1.y + bp[5]);
    v[6] = elu1(acc1.z + bp[6]); v[7] = elu1(acc1.w + bp[7]);

    if (writeH) {
        float4 o0 = {v[0], v[1], v[2], v[3]};
        float4 o1 = {v[4], v[5], v[6], v[7]};
        *(float4*)(g_h + (size_t)n * HC_ + lane * 8)     = o0;
        *(float4*)(g_h + (size_t)n * HC_ + lane * 8 + 4) = o1;
    }

    const float* pw = poolw + lane * 8;
    float p = v[0]*pw[0] + v[1]*pw[1] + v[2]*pw[2] + v[3]*pw[3]
            + v[4]*pw[4] + v[5]*pw[5] + v[6]*pw[6] + v[7]*pw[7];
#pragma unroll
    for (int off = 16; off >= 1; off >>= 1)
        p += __shfl_xor_sync(0xffffffffu, p, off);
    if (lane == 0)
        g_feat[(n >> 11) * (3 * N_) + seg * N_ + (n & 2047)] = p + poolb[0];
}

// ---------------- x0: per-node mean ---------------------------------------
__global__ void k_x0(const float* __restrict__ x) {
    int n = (blockIdx.x * blockDim.x + threadIdx.x) >> 5;
    int lane = threadIdx.x & 31;
    if (n >= NT_) return;
    float4 v = *(const float4*)(x + (size_t)n * INCH_ + lane * 4);
    float s = v.x + v.y + v.z + v.w;
#pragma unroll
    for (int off = 16; off >= 1; off >>= 1)
        s += __shfl_xor_sync(0xffffffffu, s, off);
    if (lane == 0)
        g_feat[(n >> 11) * (3 * N_) + (n & 2047)] = s * (1.f / 128.f);
}

// ---------------- LayerNorm in place ---------------------------------------
__global__ void k_ln(const float* __restrict__ w, const float* __restrict__ b) {
    __shared__ float red[8];
    __shared__ float tot;
    int row = blockIdx.x;                          // 0..47
    float* p = g_feat + (row / 3) * (3 * N_) + (row % 3) * N_;
    int t = threadIdx.x;                           // 256
    float v[8];
    float s = 0.f;
#pragma unroll
    for (int i = 0; i < 8; i++) { v[i] = p[t + 256 * i]; s += v[i]; }
#pragma unroll
    for (int off = 16; off >= 1; off >>= 1) s += __shfl_xor_sync(0xffffffffu, s, off);
    if ((t & 31) == 0) red[t >> 5] = s;
    __syncthreads();
    if (t == 0) { float z = 0.f; for (int i = 0; i < 8; i++) z += red[i]; tot = z; }
    __syncthreads();
    float mu = tot * (1.f / 2048.f);
    float q = 0.f;
#pragma unroll
    for (int i = 0; i < 8; i++) { float d = v[i] - mu; q += d * d; }
#pragma unroll
    for (int off = 16; off >= 1; off >>= 1) q += __shfl_xor_sync(0xffffffffu, q, off);
    __syncthreads();
    if ((t & 31) == 0) red[t >> 5] = q;
    __syncthreads();
    if (t == 0) { float z = 0.f; for (int i = 0; i < 8; i++) z += red[i]; tot = z; }
    __syncthreads();
    float r = rsqrtf(tot * (1.f / 2048.f) + 1e-5f);
#pragma unroll
    for (int i = 0; i < 8; i++) {
        int idx = t + 256 * i;
        p[idx] = (v[i] - mu) * r * w[idx] + b[idx];
    }
}

// ---------------- FC partial GEMM (deterministic k-splits) ------------------
__global__ void k_fc(int which, const float* __restrict__ W, int K, int Ncol) {
    const float* A = (which == 0) ? (const float*)g_feat
                   : (which == 1) ? (const float*)g_e0 : (const float*)g_e1;
    __shared__ float sa[16][128];
    int tid = threadIdx.x;                 // 128
    int j = blockIdx.x * 128 + tid;
    int kslab = K / gridDim.y;
    int k0 = blockIdx.y * kslab;
    float acc[16];
#pragma unroll
    for (int bi = 0; bi < 16; bi++) acc[bi] = 0.f;
    for (int kt = k0; kt < k0 + kslab; kt += 128) {
#pragma unroll
        for (int i = 0; i < 16; i++) sa[i][tid] = A[i * K + kt + tid];
        __syncthreads();
#pragma unroll 4
        for (int kk = 0; kk < 128; kk++) {
            float wv = W[(size_t)(kt + kk) * Ncol + j];
#pragma unroll
            for (int bi = 0; bi < 16; bi++) acc[bi] += sa[bi][kk] * wv;
        }
        __syncthreads();
    }
#pragma unroll
    for (int bi = 0; bi < 16; bi++)
        g_part[((size_t)blockIdx.y * 16 + bi) * Ncol + j] = acc[bi];
}

__global__ void k_fcsum(int which, const float* __restrict__ bias,
                        int Ncol, int nsplit) {
    float* C = (which == 0) ? g_e0 : (which == 1) ? g_e1 : g_e2;
    int i = blockIdx.x * blockDim.x + threadIdx.x;
    if (i < 16 * Ncol) {
        float s = 0.f;
        for (int p = 0; p < nsplit; p++) s += g_part[(size_t)p * 16 * Ncol + i];
        C[i] = elu1(s + bias[i % Ncol]);
    }
}

__global__ void k_last(const float* __restrict__ lw, const float* __restrict__ lb,
                       float* __restrict__ out, int out_n) {
    int t = threadIdx.x;
    if (t < 32 && t < out_n) {
        int bi = t >> 1, o = t & 1;
        float a = 0.f;
        for (int k = 0; k < OMIC_; k++) a += g_e2[bi * OMIC_ + k] * lw[k * 2 + o];
        out[t] = a + lb[o];
    }
}

// ---------------- driver ----------------------------------------------------
extern "C" void kernel_launch(void* const* d_in, const int* in_sizes, int n_in,
                              void* d_out, int out_size) {
    const float* x   = (const float*)d_in[0];
    const void*  ei  = d_in[1];
    const float* w1  = (const float*)d_in[2];
    const float* as1 = (const float*)d_in[3];
    const float* ad1 = (const float*)d_in[4];
    const float* b1  = (const float*)d_in[5];
    const float* p1w = (const float*)d_in[6];
    const float* p1b = (const float*)d_in[7];
    const float* w2  = (const float*)d_in[8];
    const float* as2 = (const float*)d_in[9];
    const float* ad2 = (const float*)d_in[10];
    const float* b2  = (const float*)d_in[11];
    const float* p2w = (const float*)d_in[12];
    const float* p2b = (const float*)d_in[13];
    const float* lnw = (const float*)d_in[14];
    const float* lnb = (const float*)d_in[15];
    const float* e0w = (const float*)d_in[16];
    const float* e0b = (const float*)d_in[17];
    const float* e1w = (const float*)d_in[18];
    const float* e1b = (const float*)d_in[19];
    const float* e2w = (const float*)d_in[20];
    const float* e2b = (const float*)d_in[21];
    const float* lw  = (const float*)d_in[22];
    const float* lb  = (const float*)d_in[23];
    float* out = (float*)d_out;

    k_detect<<<1, 32>>>(ei);                                   // 1
    k_zero<<<128, 256>>>();                                    // 2
    k_deg<<<E_ / 256, 256>>>(ei);                              // 3
    k_scan1<<<128, 256>>>();                                   // 4
    k_scan2<<<1, 128>>>();                                     // 5
    k_gemm_tc<<<dim3(NT_ / 128, 2), 256>>>(x, 0, w1, INCH_);   // 6  <- profiled
    k_scan3<<<128, 256>>>();                                   // 7
    k_scatter<<<E_ / 256, 256>>>(ei);                          // 8
    k_sortseg<<<NT_ / 256, 256>>>();                           // 9
    k_attn<<<NT_ / 8, 256>>>(as1, ad1);                        // 10
    k_agg<<<NT_ / 8, 256>>>(b1, p1w, p1b, 1, 1);               // 11

    k_gemm_tc<<<dim3(NT_ / 128, 2), 256>>>(nullptr, 1, w2, HC_);
    k_attn<<<NT_ / 8, 256>>>(as2, ad2);
    k_agg<<<NT_ / 8, 256>>>(b2, p2w, p2b, 0, 2);

    k_x0<<<NT_ / 8, 256>>>(x);
    k_ln<<<48, 256>>>(lnw, lnb);

    k_fc<<<dim3(FC0_ / 128, 6), 128>>>(0, e0w, 3 * N_, FC0_);
    k_fcsum<<<(16 * FC0_ + 255) / 256, 256>>>(0, e0b, FC0_, 6);
    k_fc<<<dim3(FC1_ / 128, 2), 128>>>(1, e1w, FC0_, FC1_);
    k_fcsum<<<(16 * FC1_ + 255) / 256, 256>>>(1, e1b, FC1_, 2);
    k_fc<<<dim3(OMIC_ / 128, 4), 128>>>(2, e2w, FC1_, OMIC_);
    k_fcsum<<<(16 * OMIC_ + 255) / 256, 256>>>(2, e2b, OMIC_, 4);
    k_last<<<1, 32>>>(lw, lb, out, out_size);
}